// round 17
// baseline (speedup 1.0000x reference)
#include <cuda_runtime.h>
#include <cuda_bf16.h>
#include <math.h>

#define BB 128
#define SS 512
#define EE 768
#define CC 9

#define L2E 1.4426950408889634f
#define LN2 0.6931471805599453f
#define FULLM 0xffffffffu

__device__ float g_scratch[BB];
__device__ int   g_ticket;

__device__ __forceinline__ float fast_ex2(float x) {
    float r; asm("ex2.approx.f32 %0, %1;" : "=f"(r) : "f"(x)); return r;
}

// ---------------------------------------------------------------------------
// Kernel 1: emissions = enc @ W^T + b
// warp = 4 row-groups x 8 k-sublanes; 4 rows/thread; unroll 1 to cut regs
// so 3 CTAs/SM fit (occupancy 22% -> ~33%).
// ---------------------------------------------------------------------------
__global__ __launch_bounds__(256, 3) void k_emissions(
    const float* __restrict__ enc, const float* __restrict__ W,
    const float* __restrict__ bias, float* __restrict__ em)
{
    __shared__ float4 sW[CC * 192];
    __shared__ float  sB[CC];

    int tid = threadIdx.x;
    const float4* Wv = reinterpret_cast<const float4*>(W);
    for (int i = tid; i < CC * 192; i += 256) sW[i] = Wv[i];
    if (tid < CC) sB[tid] = bias[tid];
    __syncthreads();

    int warp = tid >> 5, lane = tid & 31;
    int r = lane >> 3, sub = lane & 7;
    int rowbase = blockIdx.x * 128 + warp * 16 + r;

    const float4* e0 = reinterpret_cast<const float4*>(enc) + (size_t)rowbase * 192;

    float acc[4][CC];
#pragma unroll
    for (int j = 0; j < 4; j++)
#pragma unroll
        for (int c = 0; c < CC; c++) acc[j][c] = 0.f;

#pragma unroll 1
    for (int i = 0; i < 24; i++) {
        int k4 = i * 8 + sub;
        float4 ea = __ldg(&e0[k4]);
        float4 eb = __ldg(&e0[768 + k4]);
        float4 ec = __ldg(&e0[1536 + k4]);
        float4 ed = __ldg(&e0[2304 + k4]);
#pragma unroll
        for (int c = 0; c < CC; c++) {
            float4 w = sW[c * 192 + k4];
            acc[0][c] = fmaf(ea.x, w.x, acc[0][c]);
            acc[0][c] = fmaf(ea.y, w.y, acc[0][c]);
            acc[0][c] = fmaf(ea.z, w.z, acc[0][c]);
            acc[0][c] = fmaf(ea.w, w.w, acc[0][c]);
            acc[1][c] = fmaf(eb.x, w.x, acc[1][c]);
            acc[1][c] = fmaf(eb.y, w.y, acc[1][c]);
            acc[1][c] = fmaf(eb.z, w.z, acc[1][c]);
            acc[1][c] = fmaf(eb.w, w.w, acc[1][c]);
            acc[2][c] = fmaf(ec.x, w.x, acc[2][c]);
            acc[2][c] = fmaf(ec.y, w.y, acc[2][c]);
            acc[2][c] = fmaf(ec.z, w.z, acc[2][c]);
            acc[2][c] = fmaf(ec.w, w.w, acc[2][c]);
            acc[3][c] = fmaf(ed.x, w.x, acc[3][c]);
            acc[3][c] = fmaf(ed.y, w.y, acc[3][c]);
            acc[3][c] = fmaf(ed.z, w.z, acc[3][c]);
            acc[3][c] = fmaf(ed.w, w.w, acc[3][c]);
        }
    }

#pragma unroll
    for (int j = 0; j < 4; j++)
#pragma unroll
        for (int c = 0; c < CC; c++) {
            acc[j][c] += __shfl_xor_sync(FULLM, acc[j][c], 4);
            acc[j][c] += __shfl_xor_sync(FULLM, acc[j][c], 2);
            acc[j][c] += __shfl_xor_sync(FULLM, acc[j][c], 1);
        }

#pragma unroll
    for (int j = 0; j < 4; j++) {
        float myv = acc[j][0];
#pragma unroll
        for (int c = 1; c < 8; c++) if (sub == c) myv = acc[j][c];
        size_t obase = (size_t)(rowbase + 4 * j) * CC;
        em[obase + sub] = myv + sB[sub];
        if (sub == 0) em[obase + 8] = acc[j][8] + sB[8];
    }
}

// ---------------------------------------------------------------------------
// Kernel 2: CRF, linear-domain scaled forward/backward, TWO batches/block.
//   warp0: dual-direction chains for both batches interleaved (ILP).
//   warp1: numerators for both batches.
//   Last block folds the batch mean (ticket pattern, deterministic).
// ---------------------------------------------------------------------------
__global__ __launch_bounds__(64) void k_crf(
    const float* __restrict__ em_g,
    const float* __restrict__ startt, const float* __restrict__ endt,
    const float* __restrict__ trans,
    const void* __restrict__ tags_raw, const void* __restrict__ mask_raw,
    float* __restrict__ out)
{
    __shared__ float sexp0[SS * CC];
    __shared__ float sexp1[SS * CC];
    __shared__ unsigned char smk0[SS];
    __shared__ unsigned char smk1[SS];
    __shared__ float snum[2], sden[2];
    __shared__ float sh[2][12];

    int tid = threadIdx.x;
    int lane = tid & 31;
    int w = tid >> 5;
    int b0 = blockIdx.x * 2;

    // ---------- dtype probes ----------
    const long long* tg64 = (const long long*)tags_raw;
    const int*       tg32 = (const int*)tags_raw;
    long long tprobe = tg64[lane];
    unsigned badt = __ballot_sync(FULLM, (tprobe < 0) || (tprobe >= CC));
    bool tags64 = (badt == 0u);

    const unsigned int* m32 = (const unsigned int*)mask_raw;
    const unsigned char* m8 = (const unsigned char*)mask_raw;
    unsigned int mprobe = m32[lane];
    unsigned badm = __ballot_sync(FULLM, mprobe > 1u);
    bool mask8 = (badm != 0u);

    // ---------- stage exp(emissions) + masks ----------
    {
        const float4* s0 = reinterpret_cast<const float4*>(em_g + (size_t)b0 * SS * CC);
        const float4* s1 = reinterpret_cast<const float4*>(em_g + (size_t)(b0 + 1) * SS * CC);
        float4* d0 = reinterpret_cast<float4*>(sexp0);
        float4* d1 = reinterpret_cast<float4*>(sexp1);
        for (int i = tid; i < (SS * CC) / 4; i += 64) {
            float4 t0v = __ldg(&s0[i]);
            float4 t1v = __ldg(&s1[i]);
            float4 o0, o1;
            o0.x = fast_ex2(t0v.x * L2E); o0.y = fast_ex2(t0v.y * L2E);
            o0.z = fast_ex2(t0v.z * L2E); o0.w = fast_ex2(t0v.w * L2E);
            o1.x = fast_ex2(t1v.x * L2E); o1.y = fast_ex2(t1v.y * L2E);
            o1.z = fast_ex2(t1v.z * L2E); o1.w = fast_ex2(t1v.w * L2E);
            d0[i] = o0; d1[i] = o1;
        }
        if (mask8) {
            const unsigned int* ms0 = reinterpret_cast<const unsigned int*>(m8 + (size_t)b0 * SS);
            const unsigned int* ms1 = reinterpret_cast<const unsigned int*>(m8 + (size_t)(b0 + 1) * SS);
            unsigned int* md0 = reinterpret_cast<unsigned int*>(smk0);
            unsigned int* md1 = reinterpret_cast<unsigned int*>(smk1);
            for (int i = tid; i < SS / 4; i += 64) { md0[i] = __ldg(&ms0[i]); md1[i] = __ldg(&ms1[i]); }
        } else {
            const unsigned int* ms0 = m32 + (size_t)b0 * SS;
            const unsigned int* ms1 = m32 + (size_t)(b0 + 1) * SS;
            for (int s = tid; s < SS; s += 64) {
                smk0[s] = (unsigned char)(__ldg(&ms0[s]) != 0u);
                smk1[s] = (unsigned char)(__ldg(&ms1[s]) != 0u);
            }
        }
    }
    __syncthreads();

    if (w == 1) {
        // ---------------- numerators (em from global/L2) ----------------
#pragma unroll
        for (int p = 0; p < 2; p++) {
            const long long* tb64 = tg64 + (size_t)(b0 + p) * SS;
            const int*       tb32 = tg32 + (size_t)(b0 + p) * SS;
            const float* emb = em_g + (size_t)(b0 + p) * SS * CC;
            const unsigned char* smkp = p ? smk1 : smk0;
            float pnum = 0.f;
            int plen = 0;
#pragma unroll 4
            for (int it = 0; it < SS / 32; it++) {
                int s = it * 32 + lane;
                int t = tags64 ? (int)__ldg(&tb64[s]) : __ldg(&tb32[s]);
                int mv = smkp[s];
                plen += mv;
                if (s >= 1 && mv) {
                    int tp = tags64 ? (int)__ldg(&tb64[s - 1]) : __ldg(&tb32[s - 1]);
                    pnum += __ldg(&trans[tp * CC + t]) + __ldg(&emb[s * CC + t]);
                }
            }
#pragma unroll
            for (int off = 16; off >= 1; off >>= 1) {
                pnum += __shfl_xor_sync(FULLM, pnum, off);
                plen += __shfl_xor_sync(FULLM, plen, off);
            }
            int t0 = tags64 ? (int)__ldg(&tb64[0]) : __ldg(&tb32[0]);
            int tl = tags64 ? (int)__ldg(&tb64[plen - 1]) : __ldg(&tb32[plen - 1]);
            if (lane == 0)
                snum[p] = pnum + __ldg(&startt[t0]) + __ldg(&emb[t0]) + __ldg(&endt[tl]);
        }
    } else {
        // ---------------- dual-batch linear-domain chains ----------------
        bool isf = lane < 16;
        int g = isf ? lane : (lane - 16);
        bool active = (g < CC);
        int gc = active ? g : 0;
        int sbase = isf ? 0 : 16;

        float tk[CC];
#pragma unroll
        for (int k = 0; k < CC; k++) {
            int idx = isf ? (k * CC + gc) : (gc * CC + k);
            float tv = __expf(__ldg(&trans[idx]));
            tk[k] = active ? tv : 0.f;
        }

        float est = __expf(__ldg(&startt[gc]));
        float een = __expf(__ldg(&endt[gc]));
        float vA, vB;
        if (isf) {
            vA = active ? (est * sexp0[gc]) : 0.f;
            vB = active ? (est * sexp1[gc]) : 0.f;
        } else {
            vA = active ? een : 0.f;
            vB = active ? een : 0.f;
        }
        int KA = 0, KB = 0;

        int ei  = isf ? (CC + gc) : ((SS - 1) * CC + gc);
        int dei = isf ? CC : -CC;
        int mi  = isf ? 1 : (SS - 1);
        int dmi = isf ? 1 : -1;

        auto rescale = [&]() {
            float pa = __shfl_sync(FULLM, vA, sbase);
            float pb = __shfl_sync(FULLM, vB, sbase);
            unsigned EA = (__float_as_uint(pa) >> 23) & 0xFFu;
            unsigned EB = (__float_as_uint(pb) >> 23) & 0xFFu;
            vA *= __uint_as_float((254u - EA) << 23);
            vB *= __uint_as_float((254u - EB) << 23);
            KA += (int)EA - 127;
            KB += (int)EB - 127;
        };
        auto step = [&]() {
            float ldA = sexp0[ei];
            float ldB = sexp1[ei];
            float zA = isf ? vA : (vA * ldA);
            float zB = isf ? vB : (vB * ldB);
            float a0 = __shfl_sync(FULLM, zA, sbase + 0);
            float c0 = __shfl_sync(FULLM, zB, sbase + 0);
            float a1 = __shfl_sync(FULLM, zA, sbase + 1);
            float c1 = __shfl_sync(FULLM, zB, sbase + 1);
            float a2 = __shfl_sync(FULLM, zA, sbase + 2);
            float c2 = __shfl_sync(FULLM, zB, sbase + 2);
            float a3 = __shfl_sync(FULLM, zA, sbase + 3);
            float c3 = __shfl_sync(FULLM, zB, sbase + 3);
            float a4 = __shfl_sync(FULLM, zA, sbase + 4);
            float c4 = __shfl_sync(FULLM, zB, sbase + 4);
            float a5 = __shfl_sync(FULLM, zA, sbase + 5);
            float c5 = __shfl_sync(FULLM, zB, sbase + 5);
            float a6 = __shfl_sync(FULLM, zA, sbase + 6);
            float c6 = __shfl_sync(FULLM, zB, sbase + 6);
            float a7 = __shfl_sync(FULLM, zA, sbase + 7);
            float c7 = __shfl_sync(FULLM, zB, sbase + 7);
            float a8 = __shfl_sync(FULLM, zA, sbase + 8);
            float c8 = __shfl_sync(FULLM, zB, sbase + 8);
            float dA0 = fmaf(tk[1], a1, tk[0] * a0); dA0 = fmaf(tk[2], a2, dA0);
            float dB0 = fmaf(tk[1], c1, tk[0] * c0); dB0 = fmaf(tk[2], c2, dB0);
            float dA1 = fmaf(tk[4], a4, tk[3] * a3); dA1 = fmaf(tk[5], a5, dA1);
            float dB1 = fmaf(tk[4], c4, tk[3] * c3); dB1 = fmaf(tk[5], c5, dB1);
            float dA2 = fmaf(tk[7], a7, tk[6] * a6); dA2 = fmaf(tk[8], a8, dA2);
            float dB2 = fmaf(tk[7], c7, tk[6] * c6); dB2 = fmaf(tk[8], c8, dB2);
            float dotA = dA0 + dA1 + dA2;
            float dotB = dB0 + dB1 + dB2;
            float vnA = isf ? (dotA * ldA) : dotA;
            float vnB = isf ? (dotB * ldB) : dotB;
            int uA = smk0[mi];
            int uB = smk1[mi];
            vA = uA ? vnA : vA;
            vB = uB ? vnB : vB;
            ei += dei; mi += dmi;
        };

        for (int o = 0; o < 31; o++) {
            rescale();
#pragma unroll
            for (int k = 0; k < 8; k++) step();
        }
        rescale();
#pragma unroll
        for (int k = 0; k < 7; k++) step();

        // tail forward-only step t=256 (bwd lanes keep r)
        {
            rescale();
            float ldA = sexp0[ei];
            float ldB = sexp1[ei];
            float zA = isf ? vA : (vA * ldA);
            float zB = isf ? vB : (vB * ldB);
            float a0 = __shfl_sync(FULLM, zA, sbase + 0);
            float c0 = __shfl_sync(FULLM, zB, sbase + 0);
            float a1 = __shfl_sync(FULLM, zA, sbase + 1);
            float c1 = __shfl_sync(FULLM, zB, sbase + 1);
            float a2 = __shfl_sync(FULLM, zA, sbase + 2);
            float c2 = __shfl_sync(FULLM, zB, sbase + 2);
            float a3 = __shfl_sync(FULLM, zA, sbase + 3);
            float c3 = __shfl_sync(FULLM, zB, sbase + 3);
            float a4 = __shfl_sync(FULLM, zA, sbase + 4);
            float c4 = __shfl_sync(FULLM, zB, sbase + 4);
            float a5 = __shfl_sync(FULLM, zA, sbase + 5);
            float c5 = __shfl_sync(FULLM, zB, sbase + 5);
            float a6 = __shfl_sync(FULLM, zA, sbase + 6);
            float c6 = __shfl_sync(FULLM, zB, sbase + 6);
            float a7 = __shfl_sync(FULLM, zA, sbase + 7);
            float c7 = __shfl_sync(FULLM, zB, sbase + 7);
            float a8 = __shfl_sync(FULLM, zA, sbase + 8);
            float c8 = __shfl_sync(FULLM, zB, sbase + 8);
            float dA0 = fmaf(tk[1], a1, tk[0] * a0); dA0 = fmaf(tk[2], a2, dA0);
            float dB0 = fmaf(tk[1], c1, tk[0] * c0); dB0 = fmaf(tk[2], c2, dB0);
            float dA1 = fmaf(tk[4], a4, tk[3] * a3); dA1 = fmaf(tk[5], a5, dA1);
            float dB1 = fmaf(tk[4], c4, tk[3] * c3); dB1 = fmaf(tk[5], c5, dB1);
            float dA2 = fmaf(tk[7], a7, tk[6] * a6); dA2 = fmaf(tk[8], a8, dA2);
            float dB2 = fmaf(tk[7], c7, tk[6] * c6); dB2 = fmaf(tk[8], c8, dB2);
            float dotA = dA0 + dA1 + dA2;
            float dotB = dB0 + dB1 + dB2;
            int uA = smk0[mi];
            int uB = smk1[mi];
            if (isf && uA) vA = dotA * ldA;
            if (isf && uB) vB = dotB * ldB;
        }

        // combine: den = ln(sum_c p_c * r_c) + (Kf+Kb)*ln2
        int src = (lane < 16) ? (lane + 16) : lane;
        float rA = __shfl_sync(FULLM, vA, src);
        float rB = __shfl_sync(FULLM, vB, src);
        int KAb = __shfl_sync(FULLM, KA, 16);
        int KBb = __shfl_sync(FULLM, KB, 16);
        if (lane < CC) {
            sh[0][lane] = vA * rA;
            sh[1][lane] = vB * rB;
        }
        __syncwarp();
        if (lane == 0) {
            float s0 = sh[0][0], s1 = sh[1][0];
#pragma unroll
            for (int c = 1; c < CC; c++) { s0 += sh[0][c]; s1 += sh[1][c]; }
            sden[0] = logf(s0) + (float)(KA + KAb) * LN2;
            sden[1] = logf(s1) + (float)(KB + KBb) * LN2;
        }
    }
    __syncthreads();

    if (tid == 0) {
        g_scratch[b0]     = sden[0] - snum[0];
        g_scratch[b0 + 1] = sden[1] - snum[1];
        __threadfence();
        int done = atomicAdd(&g_ticket, 1);
        if (done == (BB / 2) - 1) {
            atomicExch(&g_ticket, 0);
            float s = 0.f;
            for (int i = 0; i < BB; i++) s += g_scratch[i];
            out[0] = s / (float)BB;
        }
    }
}

// emissions scratch (B*S*C floats = 2.25 MB)
__device__ float g_em[BB * SS * CC];

extern "C" void kernel_launch(void* const* d_in, const int* in_sizes, int n_in,
                              void* d_out, int out_size)
{
    const float* enc   = (const float*)d_in[0];
    const float* W     = (const float*)d_in[1];
    const float* bias  = (const float*)d_in[2];
    const float* stt   = (const float*)d_in[3];
    const float* ent   = (const float*)d_in[4];
    const float* trans = (const float*)d_in[5];
    const void*  tags  = d_in[6];
    const void*  mask  = d_in[7];
    float* out = (float*)d_out;

    float* em;
    cudaGetSymbolAddress((void**)&em, g_em);

    k_emissions<<<(BB * SS) / 128, 256>>>(enc, W, bias, em);
    k_crf<<<BB / 2, 64>>>(em, stt, ent, trans, tags, mask, out);
}